// round 14
// baseline (speedup 1.0000x reference)
#include <cuda_runtime.h>
#include <cuda_bf16.h>
#include <cstdint>
#include <math.h>

// ---------------- scratch (static device globals; no runtime alloc) ----------
__device__ float g_qkv[2 * 2048 * 3072];        // [B,N,3C] fp32
__device__ float g_vsum[32 * 64];
__device__ float g_vsum_p[32 * 16 * 64];
// packed tiled bf16 operands: tile(rt,kt) = 128 rows x 32 cols, SW64-swizzled,
// 8192 B contiguous; tile index = rt*(K/32)+kt
__device__ __nv_bfloat16 g_xh[4096 * 1024], g_xl[4096 * 1024];
__device__ __nv_bfloat16 g_w1h[3072 * 1024], g_w1l[3072 * 1024];
__device__ __nv_bfloat16 g_w2h[1024 * 1024], g_w2l[1024 * 1024];
__device__ __nv_bfloat16 g_ah[4096 * 1024], g_al[4096 * 1024];

__device__ __forceinline__ unsigned short bfbits(__nv_bfloat16 v) {
    return *reinterpret_cast<unsigned short*>(&v);
}

// ---------------- fp32 -> bf16 hi/lo split INTO packed tiled layout ----------
__global__ void split_pack(const float* __restrict__ src,
                           __nv_bfloat16* __restrict__ hi,
                           __nv_bfloat16* __restrict__ lo, int n4) {
    int i = blockIdx.x * 256 + threadIdx.x;
    if (i >= n4) return;
    const int r = i >> 8;
    const int c4 = (i & 255) << 2;
    float4 v = reinterpret_cast<const float4*>(src)[i];
    float vv[4] = {v.x, v.y, v.z, v.w};
    unsigned short hb[4], lb[4];
    #pragma unroll
    for (int j = 0; j < 4; j++) {
        __nv_bfloat16 h = __float2bfloat16_rn(vv[j]);
        __nv_bfloat16 l = __float2bfloat16_rn(vv[j] - __bfloat162float(h));
        hb[j] = bfbits(h); lb[j] = bfbits(l);
    }
    const int rt = r >> 7, rowin = r & 127;
    const int kt = c4 >> 5, colin = c4 & 31;
    uint32_t off = (uint32_t)rowin * 64 + (uint32_t)colin * 2;
    uint32_t sw = off ^ ((off >> 3) & 0x30);
    size_t dst = ((size_t)(rt * 32 + kt)) * 4096 + (sw >> 1);
    *reinterpret_cast<ushort4*>(hi + dst) = make_ushort4(hb[0], hb[1], hb[2], hb[3]);
    *reinterpret_cast<ushort4*>(lo + dst) = make_ushort4(lb[0], lb[1], lb[2], lb[3]);
}

// =============================================================================
// tcgen05 cg2 GEMM: 2-CTA cluster computes 256x256 tile; K-chunk 32; packed
// tiles + cp.async.bulk; 6-stage ring; warp-specialized control.
// =============================================================================
#define NSTG 6
#define STG_B 32768
#define GEMM_TC_SMEM (2048 + NSTG * STG_B)   // 198656

#if defined(__CUDA_ARCH__) && defined(__CUDA_ARCH_FEAT_SM103_ALL)
__device__ __forceinline__ uint32_t elect1() {
    uint32_t p;
    asm volatile("{\n\t.reg .pred p;\n\telect.sync _|p, 0xFFFFFFFF;\n\tselp.b32 %0,1,0,p;\n\t}"
                 : "=r"(p));
    return p;
}
__device__ __forceinline__ uint64_t make_desc_sw64(uint32_t addr) {
    return ((uint64_t)4 << 61) | ((uint64_t)1 << 46) | ((uint64_t)32 << 32) |
           ((uint64_t)1 << 16) | (uint64_t)((addr >> 4) & 0x3FFF);
}
__device__ __forceinline__ void mma_f16_ss_cg2(uint32_t d, uint64_t a, uint64_t b,
                                               uint32_t idesc, uint32_t acc) {
    asm volatile(
        "{\n\t.reg .pred p;\n\tsetp.ne.u32 p, %4, 0;\n\t"
        "tcgen05.mma.cta_group::2.kind::f16 [%0], %1, %2, %3, "
        "{%5,%5,%5,%5,%5,%5,%5,%5}, p;\n\t}"
        :: "r"(d), "l"(a), "l"(b), "r"(idesc), "r"(acc), "r"(0u) : "memory");
}
__device__ __forceinline__ void bulk_g2s(uint32_t dst, const void* src,
                                         uint32_t bytes, uint32_t mbar) {
    asm volatile(
        "cp.async.bulk.shared::cluster.global.mbarrier::complete_tx::bytes "
        "[%0], [%1], %2, [%3];"
        :: "r"(dst), "l"(src), "r"(bytes), "r"(mbar) : "memory");
}
#define MBAR_INIT(a, c) \
    asm volatile("mbarrier.init.shared.b64 [%0], %1;" :: "r"(a), "r"(c) : "memory")
#define MBAR_EXPECT_TX(a, bytes) \
    asm volatile("mbarrier.arrive.expect_tx.shared.b64 _, [%0], %1;" \
                 :: "r"(a), "r"(bytes) : "memory")
#define MBAR_WAIT(a, ph) do {                                                   \
    uint32_t _done = 0;                                                         \
    while (!_done) {                                                            \
        asm volatile(                                                           \
            "{\n\t.reg .pred p;\n\t"                                            \
            "mbarrier.try_wait.parity.acquire.cta.shared::cta.b64 p, [%1], %2, 0x989680;\n\t" \
            "selp.b32 %0,1,0,p;\n\t}"                                           \
            : "=r"(_done) : "r"(a), "r"((uint32_t)(ph)) : "memory");            \
    }                                                                           \
} while (0)
#define MBAR_ARRIVE_RANK0(localaddr) \
    asm volatile( \
        "{\n\t.reg .b32 ra;\n\tmapa.shared::cluster.u32 ra, %0, 0;\n\t" \
        "mbarrier.arrive.shared::cluster.b64 _, [ra];\n\t}" \
        :: "r"(localaddr) : "memory")
#define TC_COMMIT_MC2(mb) \
    asm volatile("tcgen05.commit.cta_group::2.mbarrier::arrive::one.shared::cluster.multicast::cluster.b64 [%0], %1;" \
                 :: "r"(mb), "h"((unsigned short)0x3) : "memory")
#define TC_LD_X32(r, addr)                                                      \
    asm volatile("tcgen05.ld.sync.aligned.32x32b.x32.b32 "                      \
        "{%0,%1,%2,%3,%4,%5,%6,%7,%8,%9,%10,%11,%12,%13,%14,%15,"              \
        "%16,%17,%18,%19,%20,%21,%22,%23,%24,%25,%26,%27,%28,%29,%30,%31}, [%32];" \
        : "=r"((r)[0]),"=r"((r)[1]),"=r"((r)[2]),"=r"((r)[3]),                  \
          "=r"((r)[4]),"=r"((r)[5]),"=r"((r)[6]),"=r"((r)[7]),                  \
          "=r"((r)[8]),"=r"((r)[9]),"=r"((r)[10]),"=r"((r)[11]),                \
          "=r"((r)[12]),"=r"((r)[13]),"=r"((r)[14]),"=r"((r)[15]),              \
          "=r"((r)[16]),"=r"((r)[17]),"=r"((r)[18]),"=r"((r)[19]),              \
          "=r"((r)[20]),"=r"((r)[21]),"=r"((r)[22]),"=r"((r)[23]),              \
          "=r"((r)[24]),"=r"((r)[25]),"=r"((r)[26]),"=r"((r)[27]),              \
          "=r"((r)[28]),"=r"((r)[29]),"=r"((r)[30]),"=r"((r)[31])               \
        : "r"(addr))
#define CLUSTER_SYNC_() do { \
    asm volatile("barrier.cluster.arrive.aligned;" ::: "memory"); \
    asm volatile("barrier.cluster.wait.aligned;" ::: "memory"); \
} while (0)
#endif

__global__ __launch_bounds__(128, 1) __cluster_dims__(2, 1, 1)
void gemm_tc(const __nv_bfloat16* __restrict__ Ah_, const __nv_bfloat16* __restrict__ Al_,
             const __nv_bfloat16* __restrict__ Bh_, const __nv_bfloat16* __restrict__ Bl_,
             const float* __restrict__ bias, float* __restrict__ C, int N, int K) {
#if defined(__CUDA_ARCH__) && defined(__CUDA_ARCH_FEAT_SM103_ALL)
    extern __shared__ char smem[];
    const int tid = threadIdx.x;
    const int wid = tid >> 5, lane = tid & 31;
    const int rank = blockIdx.x & 1;
    const int bn = (blockIdx.x >> 1) * 256;
    const int bm = blockIdx.y * 256 + rank * 128;
    const uint32_t sbase = (uint32_t)__cvta_generic_to_shared(smem);
    const uint32_t tiles0 = (sbase + 1024 + 1023) & ~1023u;
    const uint32_t full0 = sbase + 64, done0 = sbase + 128;
    const uint32_t rdy0 = sbase + 192, mbfin = sbase + 256;

    if (tid == 0) {
        #pragma unroll
        for (int s = 0; s < NSTG; s++) {
            MBAR_INIT(full0 + 8 * s, 1);
            MBAR_INIT(done0 + 8 * s, 1);
            MBAR_INIT(rdy0 + 8 * s, 1);
        }
        MBAR_INIT(mbfin, 1);
    }
    if (wid == 0) {
        asm volatile("tcgen05.alloc.cta_group::2.sync.aligned.shared::cta.b32 [%0], %1;"
                     :: "r"(sbase), "r"(256u) : "memory");
    }
    __syncthreads();
    uint32_t tmem;
    asm volatile("ld.shared.b32 %0, [%1];" : "=r"(tmem) : "r"(sbase));

    CLUSTER_SYNC_();

    const int nkt = K >> 5;
    const uint32_t idesc = 0x10400490u;      // f32 d, bf16 a/b, M=256, N=256

    if (wid == 1 && elect1()) {
        // ---------------- producer (both ranks): streams the ring -------------
        const int rtA = blockIdx.y * 2 + rank;
        const int rtB = (blockIdx.x >> 1) * 2 + rank;
        const __nv_bfloat16* tAh = Ah_ + (size_t)rtA * nkt * 4096;
        const __nv_bfloat16* tAl = Al_ + (size_t)rtA * nkt * 4096;
        const __nv_bfloat16* tBh = Bh_ + (size_t)rtB * nkt * 4096;
        const __nv_bfloat16* tBl = Bl_ + (size_t)rtB * nkt * 4096;
        for (int j = 0; j < nkt; j++) {
            const int s = j % NSTG;
            if (j >= NSTG) {
                MBAR_WAIT(done0 + 8 * s, ((j / NSTG) - 1) & 1);
            }
            const uint32_t sb = tiles0 + (uint32_t)s * STG_B;
            const uint32_t mb = full0 + 8 * s;
            MBAR_EXPECT_TX(mb, (uint32_t)STG_B);
            bulk_g2s(sb,          tAh + (size_t)j * 4096, 8192, mb);
            bulk_g2s(sb + 8192,   tAl + (size_t)j * 4096, 8192, mb);
            bulk_g2s(sb + 16384,  tBh + (size_t)j * 4096, 8192, mb);
            bulk_g2s(sb + 24576,  tBl + (size_t)j * 4096, 8192, mb);
        }
    } else if (wid == 0 && elect1()) {
        if (rank == 0) {
            // ---------------- consumer: MMA stream, never waits on done -------
            for (int kt = 0; kt < nkt; kt++) {
                const int s = kt % NSTG;
                const int ph = (kt / NSTG) & 1;
                MBAR_WAIT(full0 + 8 * s, ph);
                MBAR_WAIT(rdy0 + 8 * s, ph);
                const uint32_t sb = tiles0 + (uint32_t)s * STG_B;
                const uint64_t dAh = make_desc_sw64(sb);
                const uint64_t dAl = make_desc_sw64(sb + 8192);
                const uint64_t dBh = make_desc_sw64(sb + 16384);
                const uint64_t dBl = make_desc_sw64(sb + 24576);
                #pragma unroll
                for (int k = 0; k < 2; k++) {
                    const uint64_t o = 2 * k;
                    const uint32_t acc0 = (kt == 0 && k == 0) ? 0u : 1u;
                    mma_f16_ss_cg2(tmem, dAh + o, dBh + o, idesc, acc0);
                    mma_f16_ss_cg2(tmem, dAh + o, dBl + o, idesc, 1u);
                    mma_f16_ss_cg2(tmem, dAl + o, dBh + o, idesc, 1u);
                }
                TC_COMMIT_MC2(done0 + 8 * s);
                if (kt == nkt - 1) TC_COMMIT_MC2(mbfin);
            }
        } else {
            // ---------------- rank1: forward full[s] -> rank0 rdy[s] ----------
            for (int kt = 0; kt < nkt; kt++) {
                const int s = kt % NSTG;
                const int ph = (kt / NSTG) & 1;
                MBAR_WAIT(full0 + 8 * s, ph);
                MBAR_ARRIVE_RANK0(rdy0 + 8 * s);
            }
        }
    }

    MBAR_WAIT(mbfin, 0);
    asm volatile("tcgen05.fence::after_thread_sync;" ::: "memory");
    __syncthreads();

    // epilogue: each CTA reads its own 128 lanes x 256 cols
    {
        const int row = bm + wid * 32 + lane;
        float* Cr = C + (size_t)row * N + bn;
        for (int g = 0; g < 8; g++) {
            uint32_t r[32];
            TC_LD_X32(r, tmem + g * 32);
            asm volatile("tcgen05.wait::ld.sync.aligned;" ::: "memory");
            #pragma unroll
            for (int j = 0; j < 32; j += 4) {
                float4 o;
                o.x = __uint_as_float(r[j + 0]);
                o.y = __uint_as_float(r[j + 1]);
                o.z = __uint_as_float(r[j + 2]);
                o.w = __uint_as_float(r[j + 3]);
                if (bias) {
                    const float4 b4 = *reinterpret_cast<const float4*>(bias + bn + g * 32 + j);
                    o.x += b4.x; o.y += b4.y; o.z += b4.z; o.w += b4.w;
                }
                *reinterpret_cast<float4*>(Cr + g * 32 + j) = o;
            }
        }
        asm volatile("tcgen05.fence::before_thread_sync;" ::: "memory");
    }
    __syncthreads();
    if (wid == 0) {
        asm volatile("tcgen05.relinquish_alloc_permit.cta_group::2.sync.aligned;");
        asm volatile("tcgen05.dealloc.cta_group::2.sync.aligned.b32 %0, %1;"
                     :: "r"(tmem), "r"(256u));
    }
    CLUSTER_SYNC_();
#endif
}

// ---------------- V row-sum (2-stage) ----------------------------------------
__global__ void vsum_partial() {
    const int N = 2048, C3 = 3072, Dh = 64, H = 16;
    const int bh = blockIdx.x, s = blockIdx.y;
    const int b = bh / H, h = bh % H;
    const int dh = threadIdx.x;
    const float* base = g_qkv + (size_t)(b * N) * C3 + 2048 + h * Dh + dh;
    float acc = 0.0f;
    const int n0 = s * 128;
    for (int n = n0; n < n0 + 128; n++) acc += base[(size_t)n * C3];
    g_vsum_p[(bh * 16 + s) * Dh + dh] = acc;
}
__global__ void vsum_reduce() {
    const int Dh = 64;
    const int bh = blockIdx.x, dh = threadIdx.x;
    float acc = 0.0f;
    #pragma unroll
    for (int s = 0; s < 16; s++) acc += g_vsum_p[(bh * 16 + s) * Dh + dh];
    g_vsum[bh * Dh + dh] = acc;
}

// ---------------- banded attention: 32 queries/block share K/V rows ----------
// One warp per query; smem band = up to 72 rows of K and V (w<=20).
__global__ __launch_bounds__(1024)
void band_attn(const int* __restrict__ epoch_p) {
    const int N = 2048, C3 = 3072;
    const int w = (*epoch_p < 15) ? 16 : 20;

    __shared__ float sK[72 * 64];
    __shared__ float sV[72 * 64];

    const int tid = threadIdx.x;
    const int g = blockIdx.x;                 // 0 .. 32*64-1
    const int n0 = (g & 63) * 32;             // 64 groups of 32 per (b,h)
    const int bh = g >> 6;
    const int b = bh >> 4, h = bh & 15;

    const int lo = max(0, n0 - w);
    const int hi = min(N - 1, n0 + 31 + w);
    const int rows = hi - lo + 1;             // <= 72

    const float* base = g_qkv + (size_t)(b * N + lo) * C3 + 1024 + h * 64;
    for (int idx = tid; idx < rows * 16; idx += 1024) {
        const int r = idx >> 4, c4 = (idx & 15) * 4;
        *reinterpret_cast<float4*>(&sK[r * 64 + c4]) =
            *reinterpret_cast<const float4*>(base + (size_t)r * C3 + c4);
        *reinterpret_cast<float4*>(&sV[r * 64 + c4]) =
            *reinterpret_cast<const float4*>(base + (size_t)r * C3 + 1024 + c4);
    }
    __syncthreads();

    const int wid = tid >> 5, lane = tid & 31;
    const int n = n0 + wid;

    const float* qp = g_qkv + (size_t)(b * N + n) * C3 + h * 64;
    const float q0 = qp[lane], q1 = qp[lane + 32];
    const float s0 = g_vsum[bh * 64 + lane];
    const float s1 = g_vsum[bh * 64 + lane + 32];

    const int m0 = max(0, n - w);
    const int m1 = min(N - 1, n + w);

    float Mx = -INFINITY, Z = 0.0f;
    float a0 = 0.0f, a1 = 0.0f, bv0 = 0.0f, bv1 = 0.0f;

    for (int m = m0; m <= m1; m++) {
        const int r = m - lo;
        const float k0 = sK[r * 64 + lane], k1 = sK[r * 64 + lane + 32];
        const float v0 = sV[r * 64 + lane], v1 = sV[r * 64 + lane + 32];

        float p = q0 * k0 + q1 * k1;
        p += __shfl_xor_sync(0xffffffffu, p, 16);
        p += __shfl_xor_sync(0xffffffffu, p, 8);
        p += __shfl_xor_sync(0xffffffffu, p, 4);
        p += __shfl_xor_sync(0xffffffffu, p, 2);
        p += __shfl_xor_sync(0xffffffffu, p, 1);
        const float l = p * 4.0f;   // scale = Dh // H = 4

        if (l > Mx) {
            const float f = __expf(Mx - l);
            Z *= f; a0 *= f; a1 *= f;
            Mx = l;
        }
        const float e = __expf(l - Mx);
        Z += e;
        a0 = fmaf(e, v0, a0);
        a1 = fmaf(e, v1, a1);
        bv0 += v0; bv1 += v1;
    }

    const float lm = 1e-9f;
    const float cu = __expf(lm - Mx);
    const int nband = m1 - m0 + 1;
    Z += (float)(N - nband) * cu;

    const float invZ = 1.0f / Z;
    const float o0 = (a0 + cu * (s0 - bv0)) * invZ;
    const float o1 = (a1 + cu * (s1 - bv1)) * invZ;

    // packed tiled store
    const int rr = b * N + n;
    const int rt = rr >> 7, rowin = rr & 127;
    uint32_t off = (uint32_t)rowin * 64 + (uint32_t)lane * 2;
    uint32_t sw = off ^ ((off >> 3) & 0x30);
    const size_t t0 = ((size_t)(rt * 32 + 2 * h)) * 4096 + (sw >> 1);
    const size_t t1 = ((size_t)(rt * 32 + 2 * h + 1)) * 4096 + (sw >> 1);

    __nv_bfloat16 h0 = __float2bfloat16_rn(o0);
    __nv_bfloat16 l0 = __float2bfloat16_rn(o0 - __bfloat162float(h0));
    __nv_bfloat16 h1 = __float2bfloat16_rn(o1);
    __nv_bfloat16 l1 = __float2bfloat16_rn(o1 - __bfloat162float(h1));
    g_ah[t0] = h0;  g_al[t0] = l0;
    g_ah[t1] = h1;  g_al[t1] = l1;
}

// ---------------- launcher ---------------------------------------------------
extern "C" void kernel_launch(void* const* d_in, const int* in_sizes, int n_in,
                              void* d_out, int out_size) {
    const float* x      = (const float*)d_in[0];
    const float* qkv_w  = (const float*)d_in[1];
    const float* proj_w = (const float*)d_in[2];
    const float* proj_b = (const float*)d_in[3];
    const int*   epoch  = (const int*)d_in[4];

    float* qkv_buf;
    __nv_bfloat16 *xh, *xl, *w1h, *w1l, *w2h, *w2l, *ah, *al;
    cudaGetSymbolAddress((void**)&qkv_buf, g_qkv);
    cudaGetSymbolAddress((void**)&xh, g_xh);   cudaGetSymbolAddress((void**)&xl, g_xl);
    cudaGetSymbolAddress((void**)&w1h, g_w1h); cudaGetSymbolAddress((void**)&w1l, g_w1l);
    cudaGetSymbolAddress((void**)&w2h, g_w2h); cudaGetSymbolAddress((void**)&w2l, g_w2l);
    cudaGetSymbolAddress((void**)&ah, g_ah);   cudaGetSymbolAddress((void**)&al, g_al);

    cudaFuncSetAttribute(gemm_tc, cudaFuncAttributeMaxDynamicSharedMemorySize, GEMM_TC_SMEM);

    // 1) split inputs to packed tiled bf16 hi/lo
    {
        int n4 = 4096 * 256;
        split_pack<<<(n4 + 255) / 256, 256>>>(x, xh, xl, n4);
        n4 = 3072 * 256;
        split_pack<<<(n4 + 255) / 256, 256>>>(qkv_w, w1h, w1l, n4);
        n4 = 1024 * 256;
        split_pack<<<(n4 + 255) / 256, 256>>>(proj_w, w2h, w2l, n4);
    }

    // 2) qkv = x @ qkv_w^T : 2-CTA clusters, 256x256 per cluster
    gemm_tc<<<dim3(2 * (3072 / 256), 4096 / 256), 128, GEMM_TC_SMEM>>>(
        xh, xl, w1h, w1l, nullptr, qkv_buf, 3072, 1024);

    // 3) V row sums
    {
        dim3 g1(32, 16);
        vsum_partial<<<g1, 64>>>();
        vsum_reduce<<<32, 64>>>();
    }

    // 4) banded attention -> packed bf16 hi/lo att (32 queries/block)
    band_attn<<<32 * 64, 1024>>>(epoch);

    // 5) out = att @ proj_w^T + proj_b
    gemm_tc<<<dim3(2 * (1024 / 256), 4096 / 256), 128, GEMM_TC_SMEM>>>(
        ah, al, w2h, w2l, proj_b, (float*)d_out, 1024, 1024);
}

// round 15
// speedup vs baseline: 1.1191x; 1.1191x over previous
#include <cuda_runtime.h>
#include <cuda_bf16.h>
#include <cstdint>
#include <math.h>

// ---------------- scratch (static device globals; no runtime alloc) ----------
__device__ float g_qkv[2 * 2048 * 3072];        // [B,N,3C] fp32
__device__ float g_vsum[32 * 64];
__device__ float g_vsum_p[32 * 16 * 64];
// packed tiled bf16 operands: tile(rt,kt) = 128 rows x 32 cols, SW64-swizzled,
// 8192 B contiguous; tile index = rt*(K/32)+kt
__device__ __nv_bfloat16 g_xh[4096 * 1024], g_xl[4096 * 1024];
__device__ __nv_bfloat16 g_w1h[3072 * 1024], g_w1l[3072 * 1024];
__device__ __nv_bfloat16 g_w2h[1024 * 1024], g_w2l[1024 * 1024];
__device__ __nv_bfloat16 g_ah[4096 * 1024], g_al[4096 * 1024];

__device__ __forceinline__ unsigned short bfbits(__nv_bfloat16 v) {
    return *reinterpret_cast<unsigned short*>(&v);
}

// ---------------- fp32 -> bf16 hi/lo split INTO packed tiled layout ----------
__global__ void split_pack(const float* __restrict__ src,
                           __nv_bfloat16* __restrict__ hi,
                           __nv_bfloat16* __restrict__ lo, int n4) {
    int i = blockIdx.x * 256 + threadIdx.x;
    if (i >= n4) return;
    const int r = i >> 8;
    const int c4 = (i & 255) << 2;
    float4 v = reinterpret_cast<const float4*>(src)[i];
    float vv[4] = {v.x, v.y, v.z, v.w};
    unsigned short hb[4], lb[4];
    #pragma unroll
    for (int j = 0; j < 4; j++) {
        __nv_bfloat16 h = __float2bfloat16_rn(vv[j]);
        __nv_bfloat16 l = __float2bfloat16_rn(vv[j] - __bfloat162float(h));
        hb[j] = bfbits(h); lb[j] = bfbits(l);
    }
    const int rt = r >> 7, rowin = r & 127;
    const int kt = c4 >> 5, colin = c4 & 31;
    uint32_t off = (uint32_t)rowin * 64 + (uint32_t)colin * 2;
    uint32_t sw = off ^ ((off >> 3) & 0x30);
    size_t dst = ((size_t)(rt * 32 + kt)) * 4096 + (sw >> 1);
    *reinterpret_cast<ushort4*>(hi + dst) = make_ushort4(hb[0], hb[1], hb[2], hb[3]);
    *reinterpret_cast<ushort4*>(lo + dst) = make_ushort4(lb[0], lb[1], lb[2], lb[3]);
}

// =============================================================================
// tcgen05 cg2 GEMM, PERSISTENT: 74 (or fewer) 2-CTA clusters iterate tiles.
// Tile = 256x256. K-chunk 32, 5-stage ring, TMA bulk loads, double-buffered
// TMEM accumulators so epilogue (warps 0-3) overlaps next tile's MMAs.
// warp4 = producer, warp5 = consumer(rank0)/forwarder(rank1).
// =============================================================================
#define NSTG 5
#define STG_B 32768
#define GEMM_TC_SMEM (2048 + NSTG * STG_B)   // 165888

#if defined(__CUDA_ARCH__) && defined(__CUDA_ARCH_FEAT_SM103_ALL)
__device__ __forceinline__ uint32_t elect1() {
    uint32_t p;
    asm volatile("{\n\t.reg .pred p;\n\telect.sync _|p, 0xFFFFFFFF;\n\tselp.b32 %0,1,0,p;\n\t}"
                 : "=r"(p));
    return p;
}
__device__ __forceinline__ uint64_t make_desc_sw64(uint32_t addr) {
    return ((uint64_t)4 << 61) | ((uint64_t)1 << 46) | ((uint64_t)32 << 32) |
           ((uint64_t)1 << 16) | (uint64_t)((addr >> 4) & 0x3FFF);
}
__device__ __forceinline__ void mma_f16_ss_cg2(uint32_t d, uint64_t a, uint64_t b,
                                               uint32_t idesc, uint32_t acc) {
    asm volatile(
        "{\n\t.reg .pred p;\n\tsetp.ne.u32 p, %4, 0;\n\t"
        "tcgen05.mma.cta_group::2.kind::f16 [%0], %1, %2, %3, "
        "{%5,%5,%5,%5,%5,%5,%5,%5}, p;\n\t}"
        :: "r"(d), "l"(a), "l"(b), "r"(idesc), "r"(acc), "r"(0u) : "memory");
}
__device__ __forceinline__ void bulk_g2s(uint32_t dst, const void* src,
                                         uint32_t bytes, uint32_t mbar) {
    asm volatile(
        "cp.async.bulk.shared::cluster.global.mbarrier::complete_tx::bytes "
        "[%0], [%1], %2, [%3];"
        :: "r"(dst), "l"(src), "r"(bytes), "r"(mbar) : "memory");
}
#define MBAR_INIT(a, c) \
    asm volatile("mbarrier.init.shared.b64 [%0], %1;" :: "r"(a), "r"(c) : "memory")
#define MBAR_EXPECT_TX(a, bytes) \
    asm volatile("mbarrier.arrive.expect_tx.shared.b64 _, [%0], %1;" \
                 :: "r"(a), "r"(bytes) : "memory")
#define MBAR_WAIT(a, ph) do {                                                   \
    uint32_t _done = 0;                                                         \
    while (!_done) {                                                            \
        asm volatile(                                                           \
            "{\n\t.reg .pred p;\n\t"                                            \
            "mbarrier.try_wait.parity.acquire.cta.shared::cta.b64 p, [%1], %2, 0x989680;\n\t" \
            "selp.b32 %0,1,0,p;\n\t}"                                           \
            : "=r"(_done) : "r"(a), "r"((uint32_t)(ph)) : "memory");            \
    }                                                                           \
} while (0)
#define MBAR_ARRIVE_RANK0(localaddr) \
    asm volatile( \
        "{\n\t.reg .b32 ra;\n\tmapa.shared::cluster.u32 ra, %0, 0;\n\t" \
        "mbarrier.arrive.shared::cluster.b64 _, [ra];\n\t}" \
        :: "r"(localaddr) : "memory")
#define TC_COMMIT_MC2(mb) \
    asm volatile("tcgen05.commit.cta_group::2.mbarrier::arrive::one.shared::cluster.multicast::cluster.b64 [%0], %1;" \
                 :: "r"(mb), "h"((unsigned short)0x3) : "memory")
#define TC_LD_X32(r, addr)                                                      \
    asm volatile("tcgen05.ld.sync.aligned.32x32b.x32.b32 "                      \
        "{%0,%1,%2,%3,%4,%5,%6,%7,%8,%9,%10,%11,%12,%13,%14,%15,"              \
        "%16,%17,%18,%19,%20,%21,%22,%23,%24,%25,%26,%27,%28,%29,%30,%31}, [%32];" \
        : "=r"((r)[0]),"=r"((r)[1]),"=r"((r)[2]),"=r"((r)[3]),                  \
          "=r"((r)[4]),"=r"((r)[5]),"=r"((r)[6]),"=r"((r)[7]),                  \
          "=r"((r)[8]),"=r"((r)[9]),"=r"((r)[10]),"=r"((r)[11]),                \
          "=r"((r)[12]),"=r"((r)[13]),"=r"((r)[14]),"=r"((r)[15]),              \
          "=r"((r)[16]),"=r"((r)[17]),"=r"((r)[18]),"=r"((r)[19]),              \
          "=r"((r)[20]),"=r"((r)[21]),"=r"((r)[22]),"=r"((r)[23]),              \
          "=r"((r)[24]),"=r"((r)[25]),"=r"((r)[26]),"=r"((r)[27]),              \
          "=r"((r)[28]),"=r"((r)[29]),"=r"((r)[30]),"=r"((r)[31])               \
        : "r"(addr))
#define CLUSTER_SYNC_() do { \
    asm volatile("barrier.cluster.arrive.aligned;" ::: "memory"); \
    asm volatile("barrier.cluster.wait.aligned;" ::: "memory"); \
} while (0)
#endif

__global__ __launch_bounds__(192, 1) __cluster_dims__(2, 1, 1)
void gemm_tc(const __nv_bfloat16* __restrict__ Ah_, const __nv_bfloat16* __restrict__ Al_,
             const __nv_bfloat16* __restrict__ Bh_, const __nv_bfloat16* __restrict__ Bl_,
             const float* __restrict__ bias, float* __restrict__ C,
             int N, int K, int nM, int Ttot, int ncl) {
#if defined(__CUDA_ARCH__) && defined(__CUDA_ARCH_FEAT_SM103_ALL)
    extern __shared__ char smem[];
    const int tid = threadIdx.x;
    const int wid = tid >> 5, lane = tid & 31;
    const int rank = blockIdx.x & 1;
    const int c = blockIdx.x >> 1;                  // cluster id
    const uint32_t sbase = (uint32_t)__cvta_generic_to_shared(smem);
    const uint32_t tiles0 = (sbase + 1024 + 1023) & ~1023u;
    const uint32_t full0 = sbase + 64, done0 = sbase + 128, rdy0 = sbase + 192;
    const uint32_t tiled0 = sbase + 256;   // tile_done[2]
    const uint32_t epif0 = sbase + 288;    // epi_free[2] (rank0 only used)

    if (tid == 0) {
        #pragma unroll
        for (int s = 0; s < NSTG; s++) {
            MBAR_INIT(full0 + 8 * s, 1);
            MBAR_INIT(done0 + 8 * s, 1);
            MBAR_INIT(rdy0 + 8 * s, 1);
        }
        MBAR_INIT(tiled0, 1);     MBAR_INIT(tiled0 + 8, 1);
        MBAR_INIT(epif0, 2);      MBAR_INIT(epif0 + 8, 2);
    }
    if (wid == 0) {
        asm volatile("tcgen05.alloc.cta_group::2.sync.aligned.shared::cta.b32 [%0], %1;"
                     :: "r"(sbase), "r"(512u) : "memory");
    }
    __syncthreads();
    uint32_t tmem;
    asm volatile("ld.shared.b32 %0, [%1];" : "=r"(tmem) : "r"(sbase));

    CLUSTER_SYNC_();

    const int nkt = K >> 5;
    const uint32_t idesc = 0x10400490u;      // f32 d, bf16 a/b, M=256, N=256

    if (wid < 4) {
        // ---------------- epilogue crew: warps 0-3, both ranks ----------------
        int i = 0;
        for (int T = c; T < Ttot; T += ncl, i++) {
            const int tm = T % nM, tn = T / nM;
            MBAR_WAIT(tiled0 + 8 * (i & 1), (i >> 1) & 1);
            asm volatile("tcgen05.fence::after_thread_sync;" ::: "memory");
            const uint32_t dbase = tmem + (uint32_t)(i & 1) * 256;
            const int row = tm * 256 + rank * 128 + wid * 32 + lane;
            const int bn = tn * 256;
            float* Cr = C + (size_t)row * N + bn;
            for (int g = 0; g < 8; g++) {
                uint32_t r[32];
                TC_LD_X32(r, dbase + g * 32);
                asm volatile("tcgen05.wait::ld.sync.aligned;" ::: "memory");
                #pragma unroll
                for (int j = 0; j < 32; j += 4) {
                    float4 o;
                    o.x = __uint_as_float(r[j + 0]);
                    o.y = __uint_as_float(r[j + 1]);
                    o.z = __uint_as_float(r[j + 2]);
                    o.w = __uint_as_float(r[j + 3]);
                    if (bias) {
                        const float4 b4 = *reinterpret_cast<const float4*>(bias + bn + g * 32 + j);
                        o.x += b4.x; o.y += b4.y; o.z += b4.z; o.w += b4.w;
                    }
                    *reinterpret_cast<float4*>(Cr + g * 32 + j) = o;
                }
            }
            asm volatile("tcgen05.fence::before_thread_sync;" ::: "memory");
            asm volatile("bar.sync 1, 128;" ::: "memory");
            if (tid == 0) MBAR_ARRIVE_RANK0(epif0 + 8 * (i & 1));
        }
    } else if (wid == 4 && elect1()) {
        // ---------------- producer: streams chunks of all assigned tiles ------
        int q = 0;
        for (int T = c; T < Ttot; T += ncl) {
            const int tm = T % nM, tn = T / nM;
            const __nv_bfloat16* tAh = Ah_ + (size_t)(tm * 2 + rank) * nkt * 4096;
            const __nv_bfloat16* tAl = Al_ + (size_t)(tm * 2 + rank) * nkt * 4096;
            const __nv_bfloat16* tBh = Bh_ + (size_t)(tn * 2 + rank) * nkt * 4096;
            const __nv_bfloat16* tBl = Bl_ + (size_t)(tn * 2 + rank) * nkt * 4096;
            for (int j = 0; j < nkt; j++, q++) {
                const int s = q % NSTG;
                if (q >= NSTG) {
                    MBAR_WAIT(done0 + 8 * s, ((q / NSTG) - 1) & 1);
                }
                const uint32_t sb = tiles0 + (uint32_t)s * STG_B;
                const uint32_t mb = full0 + 8 * s;
                MBAR_EXPECT_TX(mb, (uint32_t)STG_B);
                bulk_g2s(sb,          tAh + (size_t)j * 4096, 8192, mb);
                bulk_g2s(sb + 8192,   tAl + (size_t)j * 4096, 8192, mb);
                bulk_g2s(sb + 16384,  tBh + (size_t)j * 4096, 8192, mb);
                bulk_g2s(sb + 24576,  tBl + (size_t)j * 4096, 8192, mb);
            }
        }
    } else if (wid == 5 && elect1()) {
        if (rank == 0) {
            // ---------------- consumer: MMA stream with dbuf handoff ----------
            int q = 0, i = 0;
            for (int T = c; T < Ttot; T += ncl, i++) {
                if (i >= 2) MBAR_WAIT(epif0 + 8 * (i & 1), ((i >> 1) - 1) & 1);
                const uint32_t dtile = tmem + (uint32_t)(i & 1) * 256;
                for (int j = 0; j < nkt; j++, q++) {
                    const int s = q % NSTG;
                    const int ph = (q / NSTG) & 1;
                    MBAR_WAIT(full0 + 8 * s, ph);
                    MBAR_WAIT(rdy0 + 8 * s, ph);
                    const uint32_t sb = tiles0 + (uint32_t)s * STG_B;
                    const uint64_t dAh = make_desc_sw64(sb);
                    const uint64_t dAl = make_desc_sw64(sb + 8192);
                    const uint64_t dBh = make_desc_sw64(sb + 16384);
                    const uint64_t dBl = make_desc_sw64(sb + 24576);
                    #pragma unroll
                    for (int k = 0; k < 2; k++) {
                        const uint64_t o = 2 * k;
                        const uint32_t acc0 = (j == 0 && k == 0) ? 0u : 1u;
                        mma_f16_ss_cg2(dtile, dAh + o, dBh + o, idesc, acc0);
                        mma_f16_ss_cg2(dtile, dAh + o, dBl + o, idesc, 1u);
                        mma_f16_ss_cg2(dtile, dAl + o, dBh + o, idesc, 1u);
                    }
                    TC_COMMIT_MC2(done0 + 8 * s);
                }
                TC_COMMIT_MC2(tiled0 + 8 * (i & 1));
            }
        } else {
            // ---------------- rank1: forward full[s] -> rank0 rdy[s] ----------
            int ntiles = 0;
            for (int T = c; T < Ttot; T += ncl) ntiles++;
            const int qtot = ntiles * nkt;
            for (int q = 0; q < qtot; q++) {
                const int s = q % NSTG;
                MBAR_WAIT(full0 + 8 * s, (q / NSTG) & 1);
                MBAR_ARRIVE_RANK0(rdy0 + 8 * s);
            }
        }
    }

    __syncthreads();
    if (wid == 0) {
        asm volatile("tcgen05.relinquish_alloc_permit.cta_group::2.sync.aligned;");
        asm volatile("tcgen05.dealloc.cta_group::2.sync.aligned.b32 %0, %1;"
                     :: "r"(tmem), "r"(512u));
    }
    CLUSTER_SYNC_();
#endif
}

// ---------------- V row-sum (2-stage) ----------------------------------------
__global__ void vsum_partial() {
    const int N = 2048, C3 = 3072, Dh = 64, H = 16;
    const int bh = blockIdx.x, s = blockIdx.y;
    const int b = bh / H, h = bh % H;
    const int dh = threadIdx.x;
    const float* base = g_qkv + (size_t)(b * N) * C3 + 2048 + h * Dh + dh;
    float acc = 0.0f;
    const int n0 = s * 128;
    for (int n = n0; n < n0 + 128; n++) acc += base[(size_t)n * C3];
    g_vsum_p[(bh * 16 + s) * Dh + dh] = acc;
}
__global__ void vsum_reduce() {
    const int Dh = 64;
    const int bh = blockIdx.x, dh = threadIdx.x;
    float acc = 0.0f;
    #pragma unroll
    for (int s = 0; s < 16; s++) acc += g_vsum_p[(bh * 16 + s) * Dh + dh];
    g_vsum[bh * Dh + dh] = acc;
}

// ---------------- banded attention: 8 queries/block share K/V rows -----------
__global__ __launch_bounds__(256)
void band_attn(const int* __restrict__ epoch_p) {
    const int N = 2048, C3 = 3072;
    const int w = (*epoch_p < 15) ? 16 : 20;

    __shared__ float sK[48 * 64];
    __shared__ float sV[48 * 64];

    const int tid = threadIdx.x;
    const int g = blockIdx.x;
    const int n0 = (g & 255) * 8;
    const int bh = g >> 8;
    const int b = bh >> 4, h = bh & 15;

    const int lo = max(0, n0 - w);
    const int hi = min(N - 1, n0 + 7 + w);
    const int rows = hi - lo + 1;

    const float* base = g_qkv + (size_t)(b * N + lo) * C3 + 1024 + h * 64;
    for (int idx = tid; idx < rows * 16; idx += 256) {
        const int r = idx >> 4, c4 = (idx & 15) * 4;
        *reinterpret_cast<float4*>(&sK[r * 64 + c4]) =
            *reinterpret_cast<const float4*>(base + (size_t)r * C3 + c4);
        *reinterpret_cast<float4*>(&sV[r * 64 + c4]) =
            *reinterpret_cast<const float4*>(base + (size_t)r * C3 + 1024 + c4);
    }
    __syncthreads();

    const int wid = tid >> 5, lane = tid & 31;
    const int n = n0 + wid;

    const float* qp = g_qkv + (size_t)(b * N + n) * C3 + h * 64;
    const float q0 = qp[lane], q1 = qp[lane + 32];
    const float s0 = g_vsum[bh * 64 + lane];
    const float s1 = g_vsum[bh * 64 + lane + 32];

    const int m0 = max(0, n - w);
    const int m1 = min(N - 1, n + w);

    float Mx = -INFINITY, Z = 0.0f;
    float a0 = 0.0f, a1 = 0.0f, bv0 = 0.0f, bv1 = 0.0f;

    for (int m = m0; m <= m1; m++) {
        const int r = m - lo;
        const float k0 = sK[r * 64 + lane], k1 = sK[r * 64 + lane + 32];
        const float v0 = sV[r * 64 + lane], v1 = sV[r * 64 + lane + 32];

        float p = q0 * k0 + q1 * k1;
        p += __shfl_xor_sync(0xffffffffu, p, 16);
        p += __shfl_xor_sync(0xffffffffu, p, 8);
        p += __shfl_xor_sync(0xffffffffu, p, 4);
        p += __shfl_xor_sync(0xffffffffu, p, 2);
        p += __shfl_xor_sync(0xffffffffu, p, 1);
        const float l = p * 4.0f;   // scale = Dh // H = 4

        if (l > Mx) {
            const float f = __expf(Mx - l);
            Z *= f; a0 *= f; a1 *= f;
            Mx = l;
        }
        const float e = __expf(l - Mx);
        Z += e;
        a0 = fmaf(e, v0, a0);
        a1 = fmaf(e, v1, a1);
        bv0 += v0; bv1 += v1;
    }

    const float lm = 1e-9f;
    const float cu = __expf(lm - Mx);
    const int nband = m1 - m0 + 1;
    Z += (float)(N - nband) * cu;

    const float invZ = 1.0f / Z;
    const float o0 = (a0 + cu * (s0 - bv0)) * invZ;
    const float o1 = (a1 + cu * (s1 - bv1)) * invZ;

    const int rr = b * N + n;
    const int rt = rr >> 7, rowin = rr & 127;
    uint32_t off = (uint32_t)rowin * 64 + (uint32_t)lane * 2;
    uint32_t sw = off ^ ((off >> 3) & 0x30);
    const size_t t0 = ((size_t)(rt * 32 + 2 * h)) * 4096 + (sw >> 1);
    const size_t t1 = ((size_t)(rt * 32 + 2 * h + 1)) * 4096 + (sw >> 1);

    __nv_bfloat16 h0 = __float2bfloat16_rn(o0);
    __nv_bfloat16 l0 = __float2bfloat16_rn(o0 - __bfloat162float(h0));
    __nv_bfloat16 h1 = __float2bfloat16_rn(o1);
    __nv_bfloat16 l1 = __float2bfloat16_rn(o1 - __bfloat162float(h1));
    g_ah[t0] = h0;  g_al[t0] = l0;
    g_ah[t1] = h1;  g_al[t1] = l1;
}

// ---------------- launcher ---------------------------------------------------
extern "C" void kernel_launch(void* const* d_in, const int* in_sizes, int n_in,
                              void* d_out, int out_size) {
    const float* x      = (const float*)d_in[0];
    const float* qkv_w  = (const float*)d_in[1];
    const float* proj_w = (const float*)d_in[2];
    const float* proj_b = (const float*)d_in[3];
    const int*   epoch  = (const int*)d_in[4];

    float* qkv_buf;
    __nv_bfloat16 *xh, *xl, *w1h, *w1l, *w2h, *w2l, *ah, *al;
    cudaGetSymbolAddress((void**)&qkv_buf, g_qkv);
    cudaGetSymbolAddress((void**)&xh, g_xh);   cudaGetSymbolAddress((void**)&xl, g_xl);
    cudaGetSymbolAddress((void**)&w1h, g_w1h); cudaGetSymbolAddress((void**)&w1l, g_w1l);
    cudaGetSymbolAddress((void**)&w2h, g_w2h); cudaGetSymbolAddress((void**)&w2l, g_w2l);
    cudaGetSymbolAddress((void**)&ah, g_ah);   cudaGetSymbolAddress((void**)&al, g_al);

    cudaFuncSetAttribute(gemm_tc, cudaFuncAttributeMaxDynamicSharedMemorySize, GEMM_TC_SMEM);

    // 1) split inputs to packed tiled bf16 hi/lo
    {
        int n4 = 4096 * 256;
        split_pack<<<(n4 + 255) / 256, 256>>>(x, xh, xl, n4);
        n4 = 3072 * 256;
        split_pack<<<(n4 + 255) / 256, 256>>>(qkv_w, w1h, w1l, n4);
        n4 = 1024 * 256;
        split_pack<<<(n4 + 255) / 256, 256>>>(proj_w, w2h, w2l, n4);
    }

    // 2) qkv = x @ qkv_w^T : persistent 74 clusters over 192 tiles (16M x 12N)
    gemm_tc<<<dim3(148, 1), 192, GEMM_TC_SMEM>>>(
        xh, xl, w1h, w1l, nullptr, qkv_buf, 3072, 1024, 16, 192, 74);

    // 3) V row sums
    {
        dim3 g1(32, 16);
        vsum_partial<<<g1, 64>>>();
        vsum_reduce<<<32, 64>>>();
    }

    // 4) banded attention -> packed bf16 hi/lo att (8 queries/block)
    band_attn<<<32 * 256, 256>>>(epoch);

    // 5) out = att @ proj_w^T + proj_b : 64 clusters over 64 tiles (16M x 4N)
    gemm_tc<<<dim3(128, 1), 192, GEMM_TC_SMEM>>>(
        ah, al, w2h, w2l, proj_b, (float*)d_out, 1024, 1024, 16, 64, 64);
}

// round 16
// speedup vs baseline: 1.1952x; 1.0680x over previous
#include <cuda_runtime.h>
#include <cuda_bf16.h>
#include <cstdint>
#include <math.h>

// ---------------- scratch (static device globals; no runtime alloc) ----------
__device__ float g_qkv[2 * 2048 * 3072];        // [B,N,3C] fp32
__device__ float g_vsum[32 * 64];
// packed tiled bf16 operands: tile(rt,kt) = 128 rows x 32 cols, SW64-swizzled,
// 8192 B contiguous; tile index = rt*(K/32)+kt
__device__ __nv_bfloat16 g_xh[4096 * 1024], g_xl[4096 * 1024];
__device__ __nv_bfloat16 g_w1h[3072 * 1024], g_w1l[3072 * 1024];
__device__ __nv_bfloat16 g_w2h[1024 * 1024], g_w2l[1024 * 1024];
__device__ __nv_bfloat16 g_ah[4096 * 1024], g_al[4096 * 1024];

__device__ __forceinline__ unsigned short bfbits(__nv_bfloat16 v) {
    return *reinterpret_cast<unsigned short*>(&v);
}

// ---------------- fp32 -> bf16 hi/lo split INTO packed tiled layout ----------
__global__ void split_pack(const float* __restrict__ src,
                           __nv_bfloat16* __restrict__ hi,
                           __nv_bfloat16* __restrict__ lo, int n4) {
    int i = blockIdx.x * 256 + threadIdx.x;
    if (i >= n4) return;
    const int r = i >> 8;
    const int c4 = (i & 255) << 2;
    float4 v = reinterpret_cast<const float4*>(src)[i];
    float vv[4] = {v.x, v.y, v.z, v.w};
    unsigned short hb[4], lb[4];
    #pragma unroll
    for (int j = 0; j < 4; j++) {
        __nv_bfloat16 h = __float2bfloat16_rn(vv[j]);
        __nv_bfloat16 l = __float2bfloat16_rn(vv[j] - __bfloat162float(h));
        hb[j] = bfbits(h); lb[j] = bfbits(l);
    }
    const int rt = r >> 7, rowin = r & 127;
    const int kt = c4 >> 5, colin = c4 & 31;
    uint32_t off = (uint32_t)rowin * 64 + (uint32_t)colin * 2;
    uint32_t sw = off ^ ((off >> 3) & 0x30);
    size_t dst = ((size_t)(rt * 32 + kt)) * 4096 + (sw >> 1);
    *reinterpret_cast<ushort4*>(hi + dst) = make_ushort4(hb[0], hb[1], hb[2], hb[3]);
    *reinterpret_cast<ushort4*>(lo + dst) = make_ushort4(lb[0], lb[1], lb[2], lb[3]);
}

// =============================================================================
// tcgen05 cg2 GEMM, PERSISTENT (unchanged from round 15 winner)
// =============================================================================
#define NSTG 5
#define STG_B 32768
#define GEMM_TC_SMEM (2048 + NSTG * STG_B)   // 165888

#if defined(__CUDA_ARCH__) && defined(__CUDA_ARCH_FEAT_SM103_ALL)
__device__ __forceinline__ uint32_t elect1() {
    uint32_t p;
    asm volatile("{\n\t.reg .pred p;\n\telect.sync _|p, 0xFFFFFFFF;\n\tselp.b32 %0,1,0,p;\n\t}"
                 : "=r"(p));
    return p;
}
__device__ __forceinline__ uint64_t make_desc_sw64(uint32_t addr) {
    return ((uint64_t)4 << 61) | ((uint64_t)1 << 46) | ((uint64_t)32 << 32) |
           ((uint64_t)1 << 16) | (uint64_t)((addr >> 4) & 0x3FFF);
}
__device__ __forceinline__ void mma_f16_ss_cg2(uint32_t d, uint64_t a, uint64_t b,
                                               uint32_t idesc, uint32_t acc) {
    asm volatile(
        "{\n\t.reg .pred p;\n\tsetp.ne.u32 p, %4, 0;\n\t"
        "tcgen05.mma.cta_group::2.kind::f16 [%0], %1, %2, %3, "
        "{%5,%5,%5,%5,%5,%5,%5,%5}, p;\n\t}"
        :: "r"(d), "l"(a), "l"(b), "r"(idesc), "r"(acc), "r"(0u) : "memory");
}
__device__ __forceinline__ void bulk_g2s(uint32_t dst, const void* src,
                                         uint32_t bytes, uint32_t mbar) {
    asm volatile(
        "cp.async.bulk.shared::cluster.global.mbarrier::complete_tx::bytes "
        "[%0], [%1], %2, [%3];"
        :: "r"(dst), "l"(src), "r"(bytes), "r"(mbar) : "memory");
}
#define MBAR_INIT(a, c) \
    asm volatile("mbarrier.init.shared.b64 [%0], %1;" :: "r"(a), "r"(c) : "memory")
#define MBAR_EXPECT_TX(a, bytes) \
    asm volatile("mbarrier.arrive.expect_tx.shared.b64 _, [%0], %1;" \
                 :: "r"(a), "r"(bytes) : "memory")
#define MBAR_WAIT(a, ph) do {                                                   \
    uint32_t _done = 0;                                                         \
    while (!_done) {                                                            \
        asm volatile(                                                           \
            "{\n\t.reg .pred p;\n\t"                                            \
            "mbarrier.try_wait.parity.acquire.cta.shared::cta.b64 p, [%1], %2, 0x989680;\n\t" \
            "selp.b32 %0,1,0,p;\n\t}"                                           \
            : "=r"(_done) : "r"(a), "r"((uint32_t)(ph)) : "memory");            \
    }                                                                           \
} while (0)
#define MBAR_ARRIVE_RANK0(localaddr) \
    asm volatile( \
        "{\n\t.reg .b32 ra;\n\tmapa.shared::cluster.u32 ra, %0, 0;\n\t" \
        "mbarrier.arrive.shared::cluster.b64 _, [ra];\n\t}" \
        :: "r"(localaddr) : "memory")
#define TC_COMMIT_MC2(mb) \
    asm volatile("tcgen05.commit.cta_group::2.mbarrier::arrive::one.shared::cluster.multicast::cluster.b64 [%0], %1;" \
                 :: "r"(mb), "h"((unsigned short)0x3) : "memory")
#define TC_LD_X32(r, addr)                                                      \
    asm volatile("tcgen05.ld.sync.aligned.32x32b.x32.b32 "                      \
        "{%0,%1,%2,%3,%4,%5,%6,%7,%8,%9,%10,%11,%12,%13,%14,%15,"              \
        "%16,%17,%18,%19,%20,%21,%22,%23,%24,%25,%26,%27,%28,%29,%30,%31}, [%32];" \
        : "=r"((r)[0]),"=r"((r)[1]),"=r"((r)[2]),"=r"((r)[3]),                  \
          "=r"((r)[4]),"=r"((r)[5]),"=r"((r)[6]),"=r"((r)[7]),                  \
          "=r"((r)[8]),"=r"((r)[9]),"=r"((r)[10]),"=r"((r)[11]),                \
          "=r"((r)[12]),"=r"((r)[13]),"=r"((r)[14]),"=r"((r)[15]),              \
          "=r"((r)[16]),"=r"((r)[17]),"=r"((r)[18]),"=r"((r)[19]),              \
          "=r"((r)[20]),"=r"((r)[21]),"=r"((r)[22]),"=r"((r)[23]),              \
          "=r"((r)[24]),"=r"((r)[25]),"=r"((r)[26]),"=r"((r)[27]),              \
          "=r"((r)[28]),"=r"((r)[29]),"=r"((r)[30]),"=r"((r)[31])               \
        : "r"(addr))
#define CLUSTER_SYNC_() do { \
    asm volatile("barrier.cluster.arrive.aligned;" ::: "memory"); \
    asm volatile("barrier.cluster.wait.aligned;" ::: "memory"); \
} while (0)
#endif

__global__ __launch_bounds__(192, 1) __cluster_dims__(2, 1, 1)
void gemm_tc(const __nv_bfloat16* __restrict__ Ah_, const __nv_bfloat16* __restrict__ Al_,
             const __nv_bfloat16* __restrict__ Bh_, const __nv_bfloat16* __restrict__ Bl_,
             const float* __restrict__ bias, float* __restrict__ C,
             int N, int K, int nM, int Ttot, int ncl) {
#if defined(__CUDA_ARCH__) && defined(__CUDA_ARCH_FEAT_SM103_ALL)
    extern __shared__ char smem[];
    const int tid = threadIdx.x;
    const int wid = tid >> 5, lane = tid & 31;
    const int rank = blockIdx.x & 1;
    const int c = blockIdx.x >> 1;
    const uint32_t sbase = (uint32_t)__cvta_generic_to_shared(smem);
    const uint32_t tiles0 = (sbase + 1024 + 1023) & ~1023u;
    const uint32_t full0 = sbase + 64, done0 = sbase + 128, rdy0 = sbase + 192;
    const uint32_t tiled0 = sbase + 256;
    const uint32_t epif0 = sbase + 288;

    if (tid == 0) {
        #pragma unroll
        for (int s = 0; s < NSTG; s++) {
            MBAR_INIT(full0 + 8 * s, 1);
            MBAR_INIT(done0 + 8 * s, 1);
            MBAR_INIT(rdy0 + 8 * s, 1);
        }
        MBAR_INIT(tiled0, 1);     MBAR_INIT(tiled0 + 8, 1);
        MBAR_INIT(epif0, 2);      MBAR_INIT(epif0 + 8, 2);
    }
    if (wid == 0) {
        asm volatile("tcgen05.alloc.cta_group::2.sync.aligned.shared::cta.b32 [%0], %1;"
                     :: "r"(sbase), "r"(512u) : "memory");
    }
    __syncthreads();
    uint32_t tmem;
    asm volatile("ld.shared.b32 %0, [%1];" : "=r"(tmem) : "r"(sbase));

    CLUSTER_SYNC_();

    const int nkt = K >> 5;
    const uint32_t idesc = 0x10400490u;      // f32 d, bf16 a/b, M=256, N=256

    if (wid < 4) {
        int i = 0;
        for (int T = c; T < Ttot; T += ncl, i++) {
            const int tm = T % nM, tn = T / nM;
            MBAR_WAIT(tiled0 + 8 * (i & 1), (i >> 1) & 1);
            asm volatile("tcgen05.fence::after_thread_sync;" ::: "memory");
            const uint32_t dbase = tmem + (uint32_t)(i & 1) * 256;
            const int row = tm * 256 + rank * 128 + wid * 32 + lane;
            const int bn = tn * 256;
            float* Cr = C + (size_t)row * N + bn;
            for (int g = 0; g < 8; g++) {
                uint32_t r[32];
                TC_LD_X32(r, dbase + g * 32);
                asm volatile("tcgen05.wait::ld.sync.aligned;" ::: "memory");
                #pragma unroll
                for (int j = 0; j < 32; j += 4) {
                    float4 o;
                    o.x = __uint_as_float(r[j + 0]);
                    o.y = __uint_as_float(r[j + 1]);
                    o.z = __uint_as_float(r[j + 2]);
                    o.w = __uint_as_float(r[j + 3]);
                    if (bias) {
                        const float4 b4 = *reinterpret_cast<const float4*>(bias + bn + g * 32 + j);
                        o.x += b4.x; o.y += b4.y; o.z += b4.z; o.w += b4.w;
                    }
                    *reinterpret_cast<float4*>(Cr + g * 32 + j) = o;
                }
            }
            asm volatile("tcgen05.fence::before_thread_sync;" ::: "memory");
            asm volatile("bar.sync 1, 128;" ::: "memory");
            if (tid == 0) MBAR_ARRIVE_RANK0(epif0 + 8 * (i & 1));
        }
    } else if (wid == 4 && elect1()) {
        int q = 0;
        for (int T = c; T < Ttot; T += ncl) {
            const int tm = T % nM, tn = T / nM;
            const __nv_bfloat16* tAh = Ah_ + (size_t)(tm * 2 + rank) * nkt * 4096;
            const __nv_bfloat16* tAl = Al_ + (size_t)(tm * 2 + rank) * nkt * 4096;
            const __nv_bfloat16* tBh = Bh_ + (size_t)(tn * 2 + rank) * nkt * 4096;
            const __nv_bfloat16* tBl = Bl_ + (size_t)(tn * 2 + rank) * nkt * 4096;
            for (int j = 0; j < nkt; j++, q++) {
                const int s = q % NSTG;
                if (q >= NSTG) {
                    MBAR_WAIT(done0 + 8 * s, ((q / NSTG) - 1) & 1);
                }
                const uint32_t sb = tiles0 + (uint32_t)s * STG_B;
                const uint32_t mb = full0 + 8 * s;
                MBAR_EXPECT_TX(mb, (uint32_t)STG_B);
                bulk_g2s(sb,          tAh + (size_t)j * 4096, 8192, mb);
                bulk_g2s(sb + 8192,   tAl + (size_t)j * 4096, 8192, mb);
                bulk_g2s(sb + 16384,  tBh + (size_t)j * 4096, 8192, mb);
                bulk_g2s(sb + 24576,  tBl + (size_t)j * 4096, 8192, mb);
            }
        }
    } else if (wid == 5 && elect1()) {
        if (rank == 0) {
            int q = 0, i = 0;
            for (int T = c; T < Ttot; T += ncl, i++) {
                if (i >= 2) MBAR_WAIT(epif0 + 8 * (i & 1), ((i >> 1) - 1) & 1);
                const uint32_t dtile = tmem + (uint32_t)(i & 1) * 256;
                for (int j = 0; j < nkt; j++, q++) {
                    const int s = q % NSTG;
                    const int ph = (q / NSTG) & 1;
                    MBAR_WAIT(full0 + 8 * s, ph);
                    MBAR_WAIT(rdy0 + 8 * s, ph);
                    const uint32_t sb = tiles0 + (uint32_t)s * STG_B;
                    const uint64_t dAh = make_desc_sw64(sb);
                    const uint64_t dAl = make_desc_sw64(sb + 8192);
                    const uint64_t dBh = make_desc_sw64(sb + 16384);
                    const uint64_t dBl = make_desc_sw64(sb + 24576);
                    #pragma unroll
                    for (int k = 0; k < 2; k++) {
                        const uint64_t o = 2 * k;
                        const uint32_t acc0 = (j == 0 && k == 0) ? 0u : 1u;
                        mma_f16_ss_cg2(dtile, dAh + o, dBh + o, idesc, acc0);
                        mma_f16_ss_cg2(dtile, dAh + o, dBl + o, idesc, 1u);
                        mma_f16_ss_cg2(dtile, dAl + o, dBh + o, idesc, 1u);
                    }
                    TC_COMMIT_MC2(done0 + 8 * s);
                }
                TC_COMMIT_MC2(tiled0 + 8 * (i & 1));
            }
        } else {
            int ntiles = 0;
            for (int T = c; T < Ttot; T += ncl) ntiles++;
            const int qtot = ntiles * nkt;
            for (int q = 0; q < qtot; q++) {
                const int s = q % NSTG;
                MBAR_WAIT(full0 + 8 * s, (q / NSTG) & 1);
                MBAR_ARRIVE_RANK0(rdy0 + 8 * s);
            }
        }
    }

    __syncthreads();
    if (wid == 0) {
        asm volatile("tcgen05.relinquish_alloc_permit.cta_group::2.sync.aligned;");
        asm volatile("tcgen05.dealloc.cta_group::2.sync.aligned.b32 %0, %1;"
                     :: "r"(tmem), "r"(512u));
    }
    CLUSTER_SYNC_();
#endif
}

// ---------------- V row-sum (single fused kernel) -----------------------------
__global__ __launch_bounds__(1024)
void vsum_kernel() {
    __shared__ float part[16][64];
    const int N = 2048, C3 = 3072, Dh = 64, H = 16;
    const int bh = blockIdx.x;
    const int b = bh / H, h = bh % H;
    const int s = threadIdx.x >> 6;       // 0..15
    const int dh = threadIdx.x & 63;
    const float* base = g_qkv + (size_t)(b * N) * C3 + 2048 + h * Dh + dh;
    float acc = 0.0f;
    const int n0 = s * 128;
    for (int n = n0; n < n0 + 128; n++) acc += base[(size_t)n * C3];
    part[s][dh] = acc;
    __syncthreads();
    if (s == 0) {
        float t = 0.0f;
        #pragma unroll
        for (int k = 0; k < 16; k++) t += part[k][dh];
        g_vsum[bh * Dh + dh] = t;
    }
}

// ---------------- banded attention v2: shuffle-free two-phase -----------------
// 8 queries/block, one warp per query. Phase 1: lane=key (2 keys/lane) computes
// logits via rotated smem dots. Phase 2: lane=dims (2d,2d+1) accumulates
// out = (sum_m (e_m - cu) v_m + cu * S) / Z.
__global__ __launch_bounds__(256)
void band_attn(const int* __restrict__ epoch_p) {
    const int N = 2048, C3 = 3072;
    const int w = (*epoch_p < 15) ? 16 : 20;

    __shared__ float sQ[8 * 64];
    __shared__ float sK[48 * 64];
    __shared__ float sV[48 * 64];
    __shared__ float sW[8 * 48];
    __shared__ float sMeta[8 * 2];        // cu, invZ per query

    const int tid = threadIdx.x;
    const int g = blockIdx.x;
    const int n0 = (g & 255) * 8;
    const int bh = g >> 8;
    const int b = bh >> 4, h = bh & 15;

    const int lo = max(0, n0 - w);
    const int hi = min(N - 1, n0 + 7 + w);
    const int rows = hi - lo + 1;         // <= 48

    // fill K/V band
    const float* base = g_qkv + (size_t)(b * N + lo) * C3 + 1024 + h * 64;
    for (int idx = tid; idx < rows * 16; idx += 256) {
        const int r = idx >> 4, c4 = (idx & 15) * 4;
        *reinterpret_cast<float4*>(&sK[r * 64 + c4]) =
            *reinterpret_cast<const float4*>(base + (size_t)r * C3 + c4);
        *reinterpret_cast<float4*>(&sV[r * 64 + c4]) =
            *reinterpret_cast<const float4*>(base + (size_t)r * C3 + 1024 + c4);
    }
    // fill Q (8 rows x 64)
    if (tid < 128) {
        const int r = tid >> 4, c4 = (tid & 15) * 4;
        *reinterpret_cast<float4*>(&sQ[r * 64 + c4]) =
            *reinterpret_cast<const float4*>(
                g_qkv + (size_t)(b * N + n0 + r) * C3 + h * 64 + c4);
    }
    __syncthreads();

    const int wq = tid >> 5, lane = tid & 31;
    const int n = n0 + wq;
    const int m0 = max(0, n - w);
    const int m1 = min(N - 1, n + w);
    const int nb = m1 - m0 + 1;           // <= 41
    const int rbase = m0 - lo;

    // ---- phase 1: logits (lane = key, 2 keys per lane) ----
    const int va = (lane < nb);
    const int vb = (lane + 32 < nb);
    const int ra = va ? (rbase + lane) : 0;
    const int rb = vb ? (rbase + lane + 32) : 0;
    const float2* kA = reinterpret_cast<const float2*>(&sK[ra * 64]);
    const float2* kB = reinterpret_cast<const float2*>(&sK[rb * 64]);
    const float2* qr = reinterpret_cast<const float2*>(&sQ[wq * 64]);
    float da = 0.0f, db = 0.0f;
    #pragma unroll
    for (int t = 0; t < 32; t++) {
        const int u = (t + lane) & 31;    // rotated float2 index: conflict-free
        const float2 qv = qr[u];
        const float2 ka = kA[u];
        const float2 kb2 = kB[u];
        da = fmaf(qv.x, ka.x, da);  da = fmaf(qv.y, ka.y, da);
        db = fmaf(qv.x, kb2.x, db); db = fmaf(qv.y, kb2.y, db);
    }
    float la = va ? da * 4.0f : -INFINITY;   // scale = Dh // H = 4
    float lb = vb ? db * 4.0f : -INFINITY;

    float mx = fmaxf(la, lb);
    #pragma unroll
    for (int o = 16; o > 0; o >>= 1)
        mx = fmaxf(mx, __shfl_xor_sync(0xffffffffu, mx, o));

    const float ea = va ? __expf(la - mx) : 0.0f;
    const float eb = vb ? __expf(lb - mx) : 0.0f;
    float zs = ea + eb;
    #pragma unroll
    for (int o = 16; o > 0; o >>= 1)
        zs += __shfl_xor_sync(0xffffffffu, zs, o);

    const float cu = __expf(1e-9f - mx);
    const float Z = zs + (float)(N - nb) * cu;

    sW[wq * 48 + lane] = va ? (ea - cu) : 0.0f;
    if (lane < 16) sW[wq * 48 + 32 + lane] = 0.0f;
    if (vb) sW[wq * 48 + 32 + lane] = eb - cu;
    if (lane == 0) { sMeta[wq * 2] = cu; sMeta[wq * 2 + 1] = 1.0f / Z; }
    __syncwarp();

    // ---- phase 2: output (lane = dim pair 2*lane, 2*lane+1) ----
    const float cu2 = sMeta[wq * 2];
    const float invZ = sMeta[wq * 2 + 1];
    const float2 S2 = *reinterpret_cast<const float2*>(&g_vsum[bh * 64 + 2 * lane]);
    float o0 = 0.0f, o1 = 0.0f;
    const float* wrow = &sW[wq * 48];
    const float2* vb2 = reinterpret_cast<const float2*>(&sV[rbase * 64 + 2 * lane]);
    for (int m = 0; m < nb; m++) {
        const float wgt = wrow[m];
        const float2 v2 = vb2[m * 32];
        o0 = fmaf(wgt, v2.x, o0);
        o1 = fmaf(wgt, v2.y, o1);
    }
    o0 = (o0 + cu2 * S2.x) * invZ;
    o1 = (o1 + cu2 * S2.y) * invZ;

    // packed tiled store: cols h*64 + 2*lane, +1 (adjacent -> ushort2)
    const int rr = b * N + n;
    const int rt = rr >> 7, rowin = rr & 127;
    uint32_t off = (uint32_t)rowin * 64 + (uint32_t)(2 * lane) * 2;
    uint32_t sw = off ^ ((off >> 3) & 0x30);
    const int kt2 = 2 * h + (lane >> 4);      // cols 2h*32 .. : lane<16 -> tile 2h
    // col index within 64: c = 2*lane; tile = (h*64 + c)/32 = 2h + (c>>5)
    // byte offset within tile: rowin*64 + (c & 31)*2
    uint32_t off2 = (uint32_t)rowin * 64 + (uint32_t)((2 * lane) & 31) * 2;
    uint32_t sw2 = off2 ^ ((off2 >> 3) & 0x30);
    const size_t t0 = ((size_t)(rt * 32 + kt2)) * 4096 + (sw2 >> 1);

    __nv_bfloat16 h0 = __float2bfloat16_rn(o0);
    __nv_bfloat16 l0 = __float2bfloat16_rn(o0 - __bfloat162float(h0));
    __nv_bfloat16 h1 = __float2bfloat16_rn(o1);
    __nv_bfloat16 l1 = __float2bfloat16_rn(o1 - __bfloat162float(h1));
    unsigned short hb2[2] = {bfbits(h0), bfbits(h1)};
    unsigned short lb2[2] = {bfbits(l0), bfbits(l1)};
    *reinterpret_cast<ushort2*>(g_ah + t0) = make_ushort2(hb2[0], hb2[1]);
    *reinterpret_cast<ushort2*>(g_al + t0) = make_ushort2(lb2[0], lb2[1]);
}

// ---------------- launcher ---------------------------------------------------
extern "C" void kernel_launch(void* const* d_in, const int* in_sizes, int n_in,
                              void* d_out, int out_size) {
    const float* x      = (const float*)d_in[0];
    const float* qkv_w  = (const float*)d_in[1];
    const float* proj_w = (const float*)d_in[2];
    const float* proj_b = (const float*)d_in[3];
    const int*   epoch  = (const int*)d_in[4];

    float* qkv_buf;
    __nv_bfloat16 *xh, *xl, *w1h, *w1l, *w2h, *w2l, *ah, *al;
    cudaGetSymbolAddress((void**)&qkv_buf, g_qkv);
    cudaGetSymbolAddress((void**)&xh, g_xh);   cudaGetSymbolAddress((void**)&xl, g_xl);
    cudaGetSymbolAddress((void**)&w1h, g_w1h); cudaGetSymbolAddress((void**)&w1l, g_w1l);
    cudaGetSymbolAddress((void**)&w2h, g_w2h); cudaGetSymbolAddress((void**)&w2l, g_w2l);
    cudaGetSymbolAddress((void**)&ah, g_ah);   cudaGetSymbolAddress((void**)&al, g_al);

    cudaFuncSetAttribute(gemm_tc, cudaFuncAttributeMaxDynamicSharedMemorySize, GEMM_TC_SMEM);

    // 1) split inputs to packed tiled bf16 hi/lo
    {
        int n4 = 4096 * 256;
        split_pack<<<(n4 + 255) / 256, 256>>>(x, xh, xl, n4);
        n4 = 3072 * 256;
        split_pack<<<(n4 + 255) / 256, 256>>>(qkv_w, w1h, w1l, n4);
        n4 = 1024 * 256;
        split_pack<<<(n4 + 255) / 256, 256>>>(proj_w, w2h, w2l, n4);
    }

    // 2) qkv = x @ qkv_w^T : persistent 74 clusters over 192 tiles (16M x 12N)
    gemm_tc<<<dim3(148, 1), 192, GEMM_TC_SMEM>>>(
        xh, xl, w1h, w1l, nullptr, qkv_buf, 3072, 1024, 16, 192, 74);

    // 3) V row sums (fused single kernel)
    vsum_kernel<<<32, 1024>>>();

    // 4) banded attention v2 -> packed bf16 hi/lo att
    band_attn<<<32 * 256, 256>>>(epoch);

    // 5) out = att @ proj_w^T + proj_b : persistent 64 clusters over 64 tiles
    gemm_tc<<<dim3(128, 1), 192, GEMM_TC_SMEM>>>(
        ah, al, w2h, w2l, proj_b, (float*)d_out, 1024, 1024, 16, 64, 64);
}

// round 17
// speedup vs baseline: 1.2314x; 1.0302x over previous
#include <cuda_runtime.h>
#include <cuda_bf16.h>
#include <cstdint>
#include <math.h>

// ---------------- scratch (static device globals; no runtime alloc) ----------
__device__ float g_qkv[2 * 2048 * 3072];        // [B,N,3C] fp32
__device__ float g_vsum[32 * 64];
// packed tiled bf16 operands: tile(rt,kt) = 128 rows x 32 cols, SW64-swizzled,
// 8192 B contiguous; tile index = rt*(K/32)+kt
__device__ __nv_bfloat16 g_xh[4096 * 1024], g_xl[4096 * 1024];
__device__ __nv_bfloat16 g_w1h[3072 * 1024], g_w1l[3072 * 1024];
__device__ __nv_bfloat16 g_w2h[1024 * 1024], g_w2l[1024 * 1024];
__device__ __nv_bfloat16 g_ah[4096 * 1024], g_al[4096 * 1024];

__device__ __forceinline__ unsigned short bfbits(__nv_bfloat16 v) {
    return *reinterpret_cast<unsigned short*>(&v);
}

// ---------------- fused fp32 -> bf16 hi/lo split (all 3 tensors) -------------
// region 0: x (4096 rows), 1: qkv_w (3072), 2: proj_w (1024). K=1024 each.
__global__ void split_pack_all(const float* __restrict__ s0,
                               const float* __restrict__ s1,
                               const float* __restrict__ s2) {
    int i = blockIdx.x * 256 + threadIdx.x;     // float4 index, total 8192*256
    const float* src;
    __nv_bfloat16 *hi, *lo;
    if (i < 4096 * 256) {
        src = s0; hi = g_xh; lo = g_xl;
    } else if (i < (4096 + 3072) * 256) {
        i -= 4096 * 256; src = s1; hi = g_w1h; lo = g_w1l;
    } else {
        i -= (4096 + 3072) * 256;
        if (i >= 1024 * 256) return;
        src = s2; hi = g_w2h; lo = g_w2l;
    }
    const int r = i >> 8;
    const int c4 = (i & 255) << 2;
    float4 v = reinterpret_cast<const float4*>(src)[i];
    float vv[4] = {v.x, v.y, v.z, v.w};
    unsigned short hb[4], lb[4];
    #pragma unroll
    for (int j = 0; j < 4; j++) {
        __nv_bfloat16 h = __float2bfloat16_rn(vv[j]);
        __nv_bfloat16 l = __float2bfloat16_rn(vv[j] - __bfloat162float(h));
        hb[j] = bfbits(h); lb[j] = bfbits(l);
    }
    const int rt = r >> 7, rowin = r & 127;
    const int kt = c4 >> 5, colin = c4 & 31;
    uint32_t off = (uint32_t)rowin * 64 + (uint32_t)colin * 2;
    uint32_t sw = off ^ ((off >> 3) & 0x30);
    size_t dst = ((size_t)(rt * 32 + kt)) * 4096 + (sw >> 1);
    *reinterpret_cast<ushort4*>(hi + dst) = make_ushort4(hb[0], hb[1], hb[2], hb[3]);
    *reinterpret_cast<ushort4*>(lo + dst) = make_ushort4(lb[0], lb[1], lb[2], lb[3]);
}

// =============================================================================
// tcgen05 cg2 GEMM, PERSISTENT (unchanged from round 15/16 winner)
// =============================================================================
#define NSTG 5
#define STG_B 32768
#define GEMM_TC_SMEM (2048 + NSTG * STG_B)   // 165888

#if defined(__CUDA_ARCH__) && defined(__CUDA_ARCH_FEAT_SM103_ALL)
__device__ __forceinline__ uint32_t elect1() {
    uint32_t p;
    asm volatile("{\n\t.reg .pred p;\n\telect.sync _|p, 0xFFFFFFFF;\n\tselp.b32 %0,1,0,p;\n\t}"
                 : "=r"(p));
    return p;
}
__device__ __forceinline__ uint64_t make_desc_sw64(uint32_t addr) {
    return ((uint64_t)4 << 61) | ((uint64_t)1 << 46) | ((uint64_t)32 << 32) |
           ((uint64_t)1 << 16) | (uint64_t)((addr >> 4) & 0x3FFF);
}
__device__ __forceinline__ void mma_f16_ss_cg2(uint32_t d, uint64_t a, uint64_t b,
                                               uint32_t idesc, uint32_t acc) {
    asm volatile(
        "{\n\t.reg .pred p;\n\tsetp.ne.u32 p, %4, 0;\n\t"
        "tcgen05.mma.cta_group::2.kind::f16 [%0], %1, %2, %3, "
        "{%5,%5,%5,%5,%5,%5,%5,%5}, p;\n\t}"
        :: "r"(d), "l"(a), "l"(b), "r"(idesc), "r"(acc), "r"(0u) : "memory");
}
__device__ __forceinline__ void bulk_g2s(uint32_t dst, const void* src,
                                         uint32_t bytes, uint32_t mbar) {
    asm volatile(
        "cp.async.bulk.shared::cluster.global.mbarrier::complete_tx::bytes "
        "[%0], [%1], %2, [%3];"
        :: "r"(dst), "l"(src), "r"(bytes), "r"(mbar) : "memory");
}
#define MBAR_INIT(a, c) \
    asm volatile("mbarrier.init.shared.b64 [%0], %1;" :: "r"(a), "r"(c) : "memory")
#define MBAR_EXPECT_TX(a, bytes) \
    asm volatile("mbarrier.arrive.expect_tx.shared.b64 _, [%0], %1;" \
                 :: "r"(a), "r"(bytes) : "memory")
#define MBAR_WAIT(a, ph) do {                                                   \
    uint32_t _done = 0;                                                         \
    while (!_done) {                                                            \
        asm volatile(                                                           \
            "{\n\t.reg .pred p;\n\t"                                            \
            "mbarrier.try_wait.parity.acquire.cta.shared::cta.b64 p, [%1], %2, 0x989680;\n\t" \
            "selp.b32 %0,1,0,p;\n\t}"                                           \
            : "=r"(_done) : "r"(a), "r"((uint32_t)(ph)) : "memory");            \
    }                                                                           \
} while (0)
#define MBAR_ARRIVE_RANK0(localaddr) \
    asm volatile( \
        "{\n\t.reg .b32 ra;\n\tmapa.shared::cluster.u32 ra, %0, 0;\n\t" \
        "mbarrier.arrive.shared::cluster.b64 _, [ra];\n\t}" \
        :: "r"(localaddr) : "memory")
#define TC_COMMIT_MC2(mb) \
    asm volatile("tcgen05.commit.cta_group::2.mbarrier::arrive::one.shared::cluster.multicast::cluster.b64 [%0], %1;" \
                 :: "r"(mb), "h"((unsigned short)0x3) : "memory")
#define TC_LD_X32(r, addr)                                                      \
    asm volatile("tcgen05.ld.sync.aligned.32x32b.x32.b32 "                      \
        "{%0,%1,%2,%3,%4,%5,%6,%7,%8,%9,%10,%11,%12,%13,%14,%15,"              \
        "%16,%17,%18,%19,%20,%21,%22,%23,%24,%25,%26,%27,%28,%29,%30,%31}, [%32];" \
        : "=r"((r)[0]),"=r"((r)[1]),"=r"((r)[2]),"=r"((r)[3]),                  \
          "=r"((r)[4]),"=r"((r)[5]),"=r"((r)[6]),"=r"((r)[7]),                  \
          "=r"((r)[8]),"=r"((r)[9]),"=r"((r)[10]),"=r"((r)[11]),                \
          "=r"((r)[12]),"=r"((r)[13]),"=r"((r)[14]),"=r"((r)[15]),              \
          "=r"((r)[16]),"=r"((r)[17]),"=r"((r)[18]),"=r"((r)[19]),              \
          "=r"((r)[20]),"=r"((r)[21]),"=r"((r)[22]),"=r"((r)[23]),              \
          "=r"((r)[24]),"=r"((r)[25]),"=r"((r)[26]),"=r"((r)[27]),              \
          "=r"((r)[28]),"=r"((r)[29]),"=r"((r)[30]),"=r"((r)[31])               \
        : "r"(addr))
#define CLUSTER_SYNC_() do { \
    asm volatile("barrier.cluster.arrive.aligned;" ::: "memory"); \
    asm volatile("barrier.cluster.wait.aligned;" ::: "memory"); \
} while (0)
#endif

__global__ __launch_bounds__(192, 1) __cluster_dims__(2, 1, 1)
void gemm_tc(const __nv_bfloat16* __restrict__ Ah_, const __nv_bfloat16* __restrict__ Al_,
             const __nv_bfloat16* __restrict__ Bh_, const __nv_bfloat16* __restrict__ Bl_,
             const float* __restrict__ bias, float* __restrict__ C,
             int N, int K, int nM, int Ttot, int ncl) {
#if defined(__CUDA_ARCH__) && defined(__CUDA_ARCH_FEAT_SM103_ALL)
    extern __shared__ char smem[];
    const int tid = threadIdx.x;
    const int wid = tid >> 5, lane = tid & 31;
    const int rank = blockIdx.x & 1;
    const int c = blockIdx.x >> 1;
    const uint32_t sbase = (uint32_t)__cvta_generic_to_shared(smem);
    const uint32_t tiles0 = (sbase + 1024 + 1023) & ~1023u;
    const uint32_t full0 = sbase + 64, done0 = sbase + 128, rdy0 = sbase + 192;
    const uint32_t tiled0 = sbase + 256;
    const uint32_t epif0 = sbase + 288;

    if (tid == 0) {
        #pragma unroll
        for (int s = 0; s < NSTG; s++) {
            MBAR_INIT(full0 + 8 * s, 1);
            MBAR_INIT(done0 + 8 * s, 1);
            MBAR_INIT(rdy0 + 8 * s, 1);
        }
        MBAR_INIT(tiled0, 1);     MBAR_INIT(tiled0 + 8, 1);
        MBAR_INIT(epif0, 2);      MBAR_INIT(epif0 + 8, 2);
    }
    if (wid == 0) {
        asm volatile("tcgen05.alloc.cta_group::2.sync.aligned.shared::cta.b32 [%0], %1;"
                     :: "r"(sbase), "r"(512u) : "memory");
    }
    __syncthreads();
    uint32_t tmem;
    asm volatile("ld.shared.b32 %0, [%1];" : "=r"(tmem) : "r"(sbase));

    CLUSTER_SYNC_();

    const int nkt = K >> 5;
    const uint32_t idesc = 0x10400490u;      // f32 d, bf16 a/b, M=256, N=256

    if (wid < 4) {
        int i = 0;
        for (int T = c; T < Ttot; T += ncl, i++) {
            const int tm = T % nM, tn = T / nM;
            MBAR_WAIT(tiled0 + 8 * (i & 1), (i >> 1) & 1);
            asm volatile("tcgen05.fence::after_thread_sync;" ::: "memory");
            const uint32_t dbase = tmem + (uint32_t)(i & 1) * 256;
            const int row = tm * 256 + rank * 128 + wid * 32 + lane;
            const int bn = tn * 256;
            float* Cr = C + (size_t)row * N + bn;
            for (int g = 0; g < 8; g++) {
                uint32_t r[32];
                TC_LD_X32(r, dbase + g * 32);
                asm volatile("tcgen05.wait::ld.sync.aligned;" ::: "memory");
                #pragma unroll
                for (int j = 0; j < 32; j += 4) {
                    float4 o;
                    o.x = __uint_as_float(r[j + 0]);
                    o.y = __uint_as_float(r[j + 1]);
                    o.z = __uint_as_float(r[j + 2]);
                    o.w = __uint_as_float(r[j + 3]);
                    if (bias) {
                        const float4 b4 = *reinterpret_cast<const float4*>(bias + bn + g * 32 + j);
                        o.x += b4.x; o.y += b4.y; o.z += b4.z; o.w += b4.w;
                    }
                    *reinterpret_cast<float4*>(Cr + g * 32 + j) = o;
                }
            }
            asm volatile("tcgen05.fence::before_thread_sync;" ::: "memory");
            asm volatile("bar.sync 1, 128;" ::: "memory");
            if (tid == 0) MBAR_ARRIVE_RANK0(epif0 + 8 * (i & 1));
        }
    } else if (wid == 4 && elect1()) {
        int q = 0;
        for (int T = c; T < Ttot; T += ncl) {
            const int tm = T % nM, tn = T / nM;
            const __nv_bfloat16* tAh = Ah_ + (size_t)(tm * 2 + rank) * nkt * 4096;
            const __nv_bfloat16* tAl = Al_ + (size_t)(tm * 2 + rank) * nkt * 4096;
            const __nv_bfloat16* tBh = Bh_ + (size_t)(tn * 2 + rank) * nkt * 4096;
            const __nv_bfloat16* tBl = Bl_ + (size_t)(tn * 2 + rank) * nkt * 4096;
            for (int j = 0; j < nkt; j++, q++) {
                const int s = q % NSTG;
                if (q >= NSTG) {
                    MBAR_WAIT(done0 + 8 * s, ((q / NSTG) - 1) & 1);
                }
                const uint32_t sb = tiles0 + (uint32_t)s * STG_B;
                const uint32_t mb = full0 + 8 * s;
                MBAR_EXPECT_TX(mb, (uint32_t)STG_B);
                bulk_g2s(sb,          tAh + (size_t)j * 4096, 8192, mb);
                bulk_g2s(sb + 8192,   tAl + (size_t)j * 4096, 8192, mb);
                bulk_g2s(sb + 16384,  tBh + (size_t)j * 4096, 8192, mb);
                bulk_g2s(sb + 24576,  tBl + (size_t)j * 4096, 8192, mb);
            }
        }
    } else if (wid == 5 && elect1()) {
        if (rank == 0) {
            int q = 0, i = 0;
            for (int T = c; T < Ttot; T += ncl, i++) {
                if (i >= 2) MBAR_WAIT(epif0 + 8 * (i & 1), ((i >> 1) - 1) & 1);
                const uint32_t dtile = tmem + (uint32_t)(i & 1) * 256;
                for (int j = 0; j < nkt; j++, q++) {
                    const int s = q % NSTG;
                    const int ph = (q / NSTG) & 1;
                    MBAR_WAIT(full0 + 8 * s, ph);
                    MBAR_WAIT(rdy0 + 8 * s, ph);
                    const uint32_t sb = tiles0 + (uint32_t)s * STG_B;
                    const uint64_t dAh = make_desc_sw64(sb);
                    const uint64_t dAl = make_desc_sw64(sb + 8192);
                    const uint64_t dBh = make_desc_sw64(sb + 16384);
                    const uint64_t dBl = make_desc_sw64(sb + 24576);
                    #pragma unroll
                    for (int k = 0; k < 2; k++) {
                        const uint64_t o = 2 * k;
                        const uint32_t acc0 = (j == 0 && k == 0) ? 0u : 1u;
                        mma_f16_ss_cg2(dtile, dAh + o, dBh + o, idesc, acc0);
                        mma_f16_ss_cg2(dtile, dAh + o, dBl + o, idesc, 1u);
                        mma_f16_ss_cg2(dtile, dAl + o, dBh + o, idesc, 1u);
                    }
                    TC_COMMIT_MC2(done0 + 8 * s);
                }
                TC_COMMIT_MC2(tiled0 + 8 * (i & 1));
            }
        } else {
            int ntiles = 0;
            for (int T = c; T < Ttot; T += ncl) ntiles++;
            const int qtot = ntiles * nkt;
            for (int q = 0; q < qtot; q++) {
                const int s = q % NSTG;
                MBAR_WAIT(full0 + 8 * s, (q / NSTG) & 1);
                MBAR_ARRIVE_RANK0(rdy0 + 8 * s);
            }
        }
    }

    __syncthreads();
    if (wid == 0) {
        asm volatile("tcgen05.relinquish_alloc_permit.cta_group::2.sync.aligned;");
        asm volatile("tcgen05.dealloc.cta_group::2.sync.aligned.b32 %0, %1;"
                     :: "r"(tmem), "r"(512u));
    }
    CLUSTER_SYNC_();
#endif
}

// ---------------- V row-sum (single fused kernel) -----------------------------
__global__ __launch_bounds__(1024)
void vsum_kernel() {
    __shared__ float part[16][64];
    const int N = 2048, C3 = 3072, Dh = 64, H = 16;
    const int bh = blockIdx.x;
    const int b = bh / H, h = bh % H;
    const int s = threadIdx.x >> 6;
    const int dh = threadIdx.x & 63;
    const float* base = g_qkv + (size_t)(b * N) * C3 + 2048 + h * Dh + dh;
    float acc = 0.0f;
    const int n0 = s * 128;
    for (int n = n0; n < n0 + 128; n++) acc += base[(size_t)n * C3];
    part[s][dh] = acc;
    __syncthreads();
    if (s == 0) {
        float t = 0.0f;
        #pragma unroll
        for (int k = 0; k < 16; k++) t += part[k][dh];
        g_vsum[bh * Dh + dh] = t;
    }
}

// ---------------- banded attention v2: 16 queries/block, shuffle-free --------
__global__ __launch_bounds__(512)
void band_attn(const int* __restrict__ epoch_p) {
    const int N = 2048, C3 = 3072;
    const int w = (*epoch_p < 15) ? 16 : 20;

    __shared__ float sQ[16 * 64];
    __shared__ float sK[56 * 64];
    __shared__ float sV[56 * 64];
    __shared__ float sW[16 * 48];
    __shared__ float sMeta[16 * 2];

    const int tid = threadIdx.x;
    const int g = blockIdx.x;                 // 0 .. 32*128-1
    const int n0 = (g & 127) * 16;            // 128 groups of 16 per (b,h)
    const int bh = g >> 7;
    const int b = bh >> 4, h = bh & 15;

    const int lo = max(0, n0 - w);
    const int hi = min(N - 1, n0 + 15 + w);
    const int rows = hi - lo + 1;             // <= 56

    // fill K/V band
    const float* base = g_qkv + (size_t)(b * N + lo) * C3 + 1024 + h * 64;
    for (int idx = tid; idx < rows * 16; idx += 512) {
        const int r = idx >> 4, c4 = (idx & 15) * 4;
        *reinterpret_cast<float4*>(&sK[r * 64 + c4]) =
            *reinterpret_cast<const float4*>(base + (size_t)r * C3 + c4);
        *reinterpret_cast<float4*>(&sV[r * 64 + c4]) =
            *reinterpret_cast<const float4*>(base + (size_t)r * C3 + 1024 + c4);
    }
    // fill Q (16 rows x 64)
    if (tid < 256) {
        const int r = tid >> 4, c4 = (tid & 15) * 4;
        *reinterpret_cast<float4*>(&sQ[r * 64 + c4]) =
            *reinterpret_cast<const float4*>(
                g_qkv + (size_t)(b * N + n0 + r) * C3 + h * 64 + c4);
    }
    __syncthreads();

    const int wq = tid >> 5, lane = tid & 31;
    const int n = n0 + wq;
    const int m0 = max(0, n - w);
    const int m1 = min(N - 1, n + w);
    const int nb = m1 - m0 + 1;               // <= 41
    const int rbase = m0 - lo;

    // ---- phase 1: logits (lane = key, 2 keys per lane) ----
    const int va = (lane < nb);
    const int vb = (lane + 32 < nb);
    const int ra = va ? (rbase + lane) : 0;
    const int rb = vb ? (rbase + lane + 32) : 0;
    const float2* kA = reinterpret_cast<const float2*>(&sK[ra * 64]);
    const float2* kB = reinterpret_cast<const float2*>(&sK[rb * 64]);
    const float2* qr = reinterpret_cast<const float2*>(&sQ[wq * 64]);
    float da = 0.0f, db = 0.0f;
    #pragma unroll
    for (int t = 0; t < 32; t++) {
        const int u = (t + lane) & 31;        // rotated index: conflict-free
        const float2 qv = qr[u];
        const float2 ka = kA[u];
        const float2 kb2 = kB[u];
        da = fmaf(qv.x, ka.x, da);  da = fmaf(qv.y, ka.y, da);
        db = fmaf(qv.x, kb2.x, db); db = fmaf(qv.y, kb2.y, db);
    }
    float la = va ? da * 4.0f : -INFINITY;    // scale = Dh // H = 4
    float lb = vb ? db * 4.0f : -INFINITY;

    float mx = fmaxf(la, lb);
    #pragma unroll
    for (int o = 16; o > 0; o >>= 1)
        mx = fmaxf(mx, __shfl_xor_sync(0xffffffffu, mx, o));

    const float ea = va ? __expf(la - mx) : 0.0f;
    const float eb = vb ? __expf(lb - mx) : 0.0f;
    float zs = ea + eb;
    #pragma unroll
    for (int o = 16; o > 0; o >>= 1)
        zs += __shfl_xor_sync(0xffffffffu, zs, o);

    const float cu = __expf(1e-9f - mx);
    const float Z = zs + (float)(N - nb) * cu;

    sW[wq * 48 + lane] = va ? (ea - cu) : 0.0f;
    if (lane < 16) sW[wq * 48 + 32 + lane] = 0.0f;
    if (vb) sW[wq * 48 + 32 + lane] = eb - cu;
    if (lane == 0) { sMeta[wq * 2] = cu; sMeta[wq * 2 + 1] = 1.0f / Z; }
    __syncwarp();

    // ---- phase 2: output (lane = dim pair 2*lane, 2*lane+1) ----
    const float cu2 = sMeta[wq * 2];
    const float invZ = sMeta[wq * 2 + 1];
    const float2 S2 = *reinterpret_cast<const float2*>(&g_vsum[bh * 64 + 2 * lane]);
    float o0 = 0.0f, o1 = 0.0f;
    const float* wrow = &sW[wq * 48];
    const float2* vb2 = reinterpret_cast<const float2*>(&sV[rbase * 64 + 2 * lane]);
    for (int m = 0; m < nb; m++) {
        const float wgt = wrow[m];
        const float2 v2 = vb2[m * 32];
        o0 = fmaf(wgt, v2.x, o0);
        o1 = fmaf(wgt, v2.y, o1);
    }
    o0 = (o0 + cu2 * S2.x) * invZ;
    o1 = (o1 + cu2 * S2.y) * invZ;

    // packed tiled store: cols h*64 + 2*lane, +1 (adjacent -> ushort2)
    const int rr = b * N + n;
    const int rt = rr >> 7, rowin = rr & 127;
    const int kt2 = 2 * h + (lane >> 4);
    uint32_t off2 = (uint32_t)rowin * 64 + (uint32_t)((2 * lane) & 31) * 2;
    uint32_t sw2 = off2 ^ ((off2 >> 3) & 0x30);
    const size_t t0 = ((size_t)(rt * 32 + kt2)) * 4096 + (sw2 >> 1);

    __nv_bfloat16 h0 = __float2bfloat16_rn(o0);
    __nv_bfloat16 l0 = __float2bfloat16_rn(o0 - __bfloat162float(h0));
    __nv_bfloat16 h1 = __float2bfloat16_rn(o1);
    __nv_bfloat16 l1 = __float2bfloat16_rn(o1 - __bfloat162float(h1));
    unsigned short hb2[2] = {bfbits(h0), bfbits(h1)};
    unsigned short lb2[2] = {bfbits(l0), bfbits(l1)};
    *reinterpret_cast<ushort2*>(g_ah + t0) = make_ushort2(hb2[0], hb2[1]);
    *reinterpret_cast<ushort2*>(g_al + t0) = make_ushort2(lb2[0], lb2[1]);
}

// ---------------- launcher ---------------------------------------------------
extern "C" void kernel_launch(void* const* d_in, const int* in_sizes, int n_in,
                              void* d_out, int out_size) {
    const float* x      = (const float*)d_in[0];
    const float* qkv_w  = (const float*)d_in[1];
    const float* proj_w = (const float*)d_in[2];
    const float* proj_b = (const float*)d_in[3];
    const int*   epoch  = (const int*)d_in[4];

    float* qkv_buf;
    __nv_bfloat16 *xh, *xl, *w1h, *w1l, *w2h, *w2l, *ah, *al;
    cudaGetSymbolAddress((void**)&qkv_buf, g_qkv);
    cudaGetSymbolAddress((void**)&xh, g_xh);   cudaGetSymbolAddress((void**)&xl, g_xl);
    cudaGetSymbolAddress((void**)&w1h, g_w1h); cudaGetSymbolAddress((void**)&w1l, g_w1l);
    cudaGetSymbolAddress((void**)&w2h, g_w2h); cudaGetSymbolAddress((void**)&w2l, g_w2l);
    cudaGetSymbolAddress((void**)&ah, g_ah);   cudaGetSymbolAddress((void**)&al, g_al);

    cudaFuncSetAttribute(gemm_tc, cudaFuncAttributeMaxDynamicSharedMemorySize, GEMM_TC_SMEM);

    // 1) fused split of all inputs to packed tiled bf16 hi/lo
    split_pack_all<<<8192, 256>>>(x, qkv_w, proj_w);

    // 2) qkv = x @ qkv_w^T : persistent 74 clusters over 192 tiles (16M x 12N)
    gemm_tc<<<dim3(148, 1), 192, GEMM_TC_SMEM>>>(
        xh, xl, w1h, w1l, nullptr, qkv_buf, 3072, 1024, 16, 192, 74);

    // 3) V row sums
    vsum_kernel<<<32, 1024>>>();

    // 4) banded attention v2 -> packed bf16 hi/lo att (16 queries/block)
    band_attn<<<32 * 128, 512>>>(epoch);

    // 5) out = att @ proj_w^T + proj_b : persistent 64 clusters over 64 tiles
    gemm_tc<<<dim3(128, 1), 192, GEMM_TC_SMEM>>>(
        ah, al, w2h, w2l, proj_b, (float*)d_out, 1024, 1024, 16, 64, 64);
}